// round 10
// baseline (speedup 1.0000x reference)
#include <cuda_runtime.h>
#include <cuda_bf16.h>
#include <cstdint>

#define NODE_DIM 128
#define EDGE_DIM 64
#define K1       192
#define N_OUT    128
#define WARP_M   16
#define NWARPS   16
#define THREADS  (NWARPS * 32)         // 512
#define CTA_M    (NWARPS * WARP_M)     // 256
#define W1_LD    200   // padded row stride (elems); 400B = 16 mod 128 -> LDSM conflict-free
#define W2_LD    136   // padded row stride (elems); 272B = 16 mod 128 -> LDSM conflict-free
#define LN_EPS   1e-5f

// ---- smem layout (bytes) ----
#define SM_W1HI 0
#define SM_W1LO (SM_W1HI + 128 * W1_LD * 2)   // 51200
#define SM_W2HI (SM_W1LO + 128 * W1_LD * 2)   // 102400
#define SM_W2LO (SM_W2HI + 128 * W2_LD * 2)   // 137216
#define SM_VEC  (SM_W2LO + 128 * W2_LD * 2)   // 172032 : b1,b2,gamma,beta (128 f32 each)
#define SMEM_BYTES (SM_VEC + 4 * 128 * 4)     // 174080

__device__ __forceinline__ uint32_t smem_u32(const void* p) {
    uint32_t a;
    asm("{ .reg .u64 t; cvta.to.shared.u64 t, %1; cvt.u32.u64 %0, t; }" : "=r"(a) : "l"(p));
    return a;
}

__device__ __forceinline__ void mma16816(float* d, const uint32_t* a, uint32_t b0, uint32_t b1) {
    asm volatile(
        "mma.sync.aligned.m16n8k16.row.col.f32.bf16.bf16.f32 "
        "{%0,%1,%2,%3},{%4,%5,%6,%7},{%8,%9},{%0,%1,%2,%3};"
        : "+f"(d[0]), "+f"(d[1]), "+f"(d[2]), "+f"(d[3])
        : "r"(a[0]), "r"(a[1]), "r"(a[2]), "r"(a[3]), "r"(b0), "r"(b1));
}

// One ldmatrix.x4: r0,r1 = hi-weights (k-half 0/1), r2,r3 = lo-weights (k-half 0/1)
__device__ __forceinline__ void ldsm_x4(uint32_t& r0, uint32_t& r1, uint32_t& r2, uint32_t& r3,
                                        uint32_t addr) {
    asm volatile("ldmatrix.sync.aligned.m8n8.x4.shared.b16 {%0,%1,%2,%3}, [%4];"
                 : "=r"(r0), "=r"(r1), "=r"(r2), "=r"(r3) : "r"(addr));
}

__device__ __forceinline__ void prefetch_l2(const void* p) {
    asm volatile("prefetch.global.L2 [%0];" :: "l"(p));
}

__device__ __forceinline__ void split_pack(float x, float y, uint32_t& hi, uint32_t& lo) {
    __nv_bfloat162 h2 = __floats2bfloat162_rn(x, y);
    float rx = x - __bfloat162float(__low2bfloat16(h2));
    float ry = y - __bfloat162float(__high2bfloat16(h2));
    __nv_bfloat162 l2 = __floats2bfloat162_rn(rx, ry);
    hi = reinterpret_cast<uint32_t&>(h2);
    lo = reinterpret_cast<uint32_t&>(l2);
}

// exact-ish silu (final layer): 2 MUFU
__device__ __forceinline__ float silu_f(float x) {
    return __fdividef(x, 1.0f + __expf(-x));
}

// fast silu (hidden layer): 1 MUFU via tanh.approx; abs err ~1e-4, attenuated by W2
__device__ __forceinline__ float silu_fast(float x) {
    float t;
    asm("tanh.approx.f32 %0, %1;" : "=f"(t) : "f"(x * 0.5f));
    return 0.5f * x * (1.0f + t);
}

__global__ __launch_bounds__(THREADS, 1)
void edge_mlp_kernel(const float* __restrict__ src, const float* __restrict__ edge,
                     const float* __restrict__ W1, const float* __restrict__ b1v,
                     const float* __restrict__ gammav, const float* __restrict__ betav,
                     const float* __restrict__ W2, const float* __restrict__ b2v,
                     float* __restrict__ out, int E, int num_tiles)
{
    extern __shared__ char smem[];
    __nv_bfloat16* w1hi = reinterpret_cast<__nv_bfloat16*>(smem + SM_W1HI);
    __nv_bfloat16* w1lo = reinterpret_cast<__nv_bfloat16*>(smem + SM_W1LO);
    __nv_bfloat16* w2hi = reinterpret_cast<__nv_bfloat16*>(smem + SM_W2HI);
    __nv_bfloat16* w2lo = reinterpret_cast<__nv_bfloat16*>(smem + SM_W2LO);
    float* s_b1 = reinterpret_cast<float*>(smem + SM_VEC);
    float* s_b2 = s_b1 + 128;
    float* s_g  = s_b1 + 256;
    float* s_bt = s_b1 + 384;

    const int tid  = threadIdx.x;
    const int lane = tid & 31;
    const int wid  = tid >> 5;
    const int g    = lane >> 2;   // 0..7
    const int t    = lane & 3;    // 0..3

    // ---- one-time weight conversion into smem (hi/lo bf16, transposed, padded) ----
    for (int i = tid; i < 128 * K1; i += THREADS) {
        int n = i / K1, k = i - n * K1;
        float w = W1[k * N_OUT + n];
        __nv_bfloat16 h = __float2bfloat16(w);
        w1hi[n * W1_LD + k] = h;
        w1lo[n * W1_LD + k] = __float2bfloat16(w - __bfloat162float(h));
    }
    for (int i = tid; i < 128 * 128; i += THREADS) {
        int n = i >> 7, k = i & 127;
        float w = W2[k * N_OUT + n];
        __nv_bfloat16 h = __float2bfloat16(w);
        w2hi[n * W2_LD + k] = h;
        w2lo[n * W2_LD + k] = __float2bfloat16(w - __bfloat162float(h));
    }
    if (tid < 128) {
        s_b1[tid] = b1v[tid];
        s_b2[tid] = b2v[tid];
        s_g[tid]  = gammav[tid];
        s_bt[tid] = betav[tid];
    }
    __syncthreads();

    // ---- per-lane ldmatrix base offsets (bytes) ----
    const int lrow  = lane & 7;
    const int lhalf = (lane >> 3) & 1;
    const int lhilo = lane >> 4;
    const uint32_t w1_base = smem_u32(smem) + SM_W1HI
                           + (uint32_t)(lrow * (W1_LD * 2) + lhalf * 16 + lhilo * (SM_W1LO - SM_W1HI));
    const uint32_t w2_base = smem_u32(smem) + SM_W2HI
                           + (uint32_t)(lrow * (W2_LD * 2) + lhalf * 16 + lhilo * (SM_W2LO - SM_W2HI));

    for (int tile = blockIdx.x; tile < num_tiles; tile += gridDim.x) {
        // ---- prefetch next tile's x rows into L2 (3 lines/lane, ~1 tile-period ahead) ----
        {
            int ntile = tile + gridDim.x;
            if (ntile < num_tiles) {
                int pr = ntile * CTA_M + wid * WARP_M + (lane >> 1);
                if (pr < E) {
                    const char* ps = (const char*)(src + (size_t)pr * NODE_DIM) + (lane & 1) * 256;
                    prefetch_l2(ps);
                    prefetch_l2(ps + 128);
                    const char* pe = (const char*)(edge + (size_t)pr * EDGE_DIM) + (lane & 1) * 128;
                    prefetch_l2(pe);
                }
            }
        }

        const int rbase = tile * CTA_M + wid * WARP_M;
        int  row0 = rbase + g;
        int  row1 = rbase + 8 + g;
        bool v0 = row0 < E, v1 = row1 < E;
        const float* sp0 = src  + (size_t)(v0 ? row0 : 0) * NODE_DIM;
        const float* sp1 = src  + (size_t)(v1 ? row1 : 0) * NODE_DIM;
        const float* ep0 = edge + (size_t)(v0 ? row0 : 0) * EDGE_DIM;
        const float* ep1 = edge + (size_t)(v1 ? row1 : 0) * EDGE_DIM;

        auto loadA = [&](int s, float2* L) {
            const float2 z = make_float2(0.f, 0.f);
            const float* p0;
            const float* p1;
            int c;
            if (s < 8) { c = 16 * s + 2 * t;       p0 = sp0 + c; p1 = sp1 + c; }
            else       { c = 16 * s - 128 + 2 * t; p0 = ep0 + c; p1 = ep1 + c; }
            L[0] = v0 ? *(const float2*)(p0)     : z;
            L[1] = v1 ? *(const float2*)(p1)     : z;
            L[2] = v0 ? *(const float2*)(p0 + 8) : z;
            L[3] = v1 ? *(const float2*)(p1 + 8) : z;
        };

        // ================= GEMM1: C1 = x(192) @ W1, 3-pass bf16 split =================
        float C1[16][4];
        #pragma unroll
        for (int j = 0; j < 16; ++j)
            #pragma unroll
            for (int q = 0; q < 4; ++q) C1[j][q] = 0.f;

        float2 cur[4], nxt[4];
        loadA(0, cur);
        #pragma unroll 1
        for (int s = 0; s < 12; ++s) {
            if (s < 11) loadA(s + 1, nxt);
            uint32_t ahi[4], alo[4];
            #pragma unroll
            for (int q = 0; q < 4; ++q) split_pack(cur[q].x, cur[q].y, ahi[q], alo[q]);
            const uint32_t base_s = w1_base + (uint32_t)(s * 32);
            #pragma unroll
            for (int j = 0; j < 16; ++j) {
                uint32_t bh0, bh1, bl0, bl1;
                ldsm_x4(bh0, bh1, bl0, bl1, base_s + (uint32_t)(j * (8 * W1_LD * 2)));
                mma16816(C1[j], ahi, bh0, bh1);
                mma16816(C1[j], ahi, bl0, bl1);
                mma16816(C1[j], alo, bh0, bh1);
            }
            #pragma unroll
            for (int q = 0; q < 4; ++q) cur[q] = nxt[q];
        }

        // ============ Epilogue 1: +b1, LayerNorm (2x shfl over t), fast SiLU, split ============
        uint32_t A2hi[2][16], A2lo[2][16];
        #pragma unroll
        for (int i = 0; i < 2; ++i) {
            float sum = 0.f, ssq = 0.f;
            #pragma unroll
            for (int j = 0; j < 16; ++j) {
                const int col = 8 * j + 2 * t;
                float x0 = C1[j][2 * i + 0] + s_b1[col];
                float x1 = C1[j][2 * i + 1] + s_b1[col + 1];
                C1[j][2 * i + 0] = x0;
                C1[j][2 * i + 1] = x1;
                sum += x0 + x1;
                ssq = fmaf(x0, x0, ssq);
                ssq = fmaf(x1, x1, ssq);
            }
            sum += __shfl_xor_sync(0xffffffffu, sum, 1);
            sum += __shfl_xor_sync(0xffffffffu, sum, 2);
            ssq += __shfl_xor_sync(0xffffffffu, ssq, 1);
            ssq += __shfl_xor_sync(0xffffffffu, ssq, 2);
            float mu  = sum * (1.f / 128.f);
            float var = ssq * (1.f / 128.f) - mu * mu;
            float rs  = rsqrtf(fmaxf(var, 0.f) + LN_EPS);
            #pragma unroll
            for (int j = 0; j < 16; ++j) {
                const int col = 8 * j + 2 * t;
                float y0 = (C1[j][2 * i + 0] - mu) * rs * s_g[col]     + s_bt[col];
                float y1 = (C1[j][2 * i + 1] - mu) * rs * s_g[col + 1] + s_bt[col + 1];
                y0 = silu_fast(y0);
                y1 = silu_fast(y1);
                split_pack(y0, y1, A2hi[i][j], A2lo[i][j]);
            }
        }

        // ================= GEMM2 (n-split halves): out = silu(h @ W2 + b2) =================
        #pragma unroll 1
        for (int hf = 0; hf < 2; ++hf) {
            float C2[8][4];
            #pragma unroll
            for (int j = 0; j < 8; ++j)
                #pragma unroll
                for (int q = 0; q < 4; ++q) C2[j][q] = 0.f;

            const uint32_t base_hf = w2_base + (uint32_t)(hf * (64 * W2_LD * 2));
            #pragma unroll
            for (int s = 0; s < 8; ++s) {
                uint32_t ah[4], al[4];
                ah[0] = A2hi[0][2 * s];     ah[1] = A2hi[1][2 * s];
                ah[2] = A2hi[0][2 * s + 1]; ah[3] = A2hi[1][2 * s + 1];
                al[0] = A2lo[0][2 * s];     al[1] = A2lo[1][2 * s];
                al[2] = A2lo[0][2 * s + 1]; al[3] = A2lo[1][2 * s + 1];
                const uint32_t base_s = base_hf + (uint32_t)(s * 32);
                #pragma unroll
                for (int j = 0; j < 8; ++j) {
                    uint32_t bh0, bh1, bl0, bl1;
                    ldsm_x4(bh0, bh1, bl0, bl1, base_s + (uint32_t)(j * (8 * W2_LD * 2)));
                    mma16816(C2[j], ah, bh0, bh1);
                    mma16816(C2[j], ah, bl0, bl1);
                    mma16816(C2[j], al, bh0, bh1);
                }
            }

            if (v0) {
                float* op = out + (size_t)row0 * N_OUT;
                #pragma unroll
                for (int j = 0; j < 8; ++j) {
                    const int col = hf * 64 + 8 * j + 2 * t;
                    *(float2*)(op + col) = make_float2(silu_f(C2[j][0] + s_b2[col]),
                                                       silu_f(C2[j][1] + s_b2[col + 1]));
                }
            }
            if (v1) {
                float* op = out + (size_t)row1 * N_OUT;
                #pragma unroll
                for (int j = 0; j < 8; ++j) {
                    const int col = hf * 64 + 8 * j + 2 * t;
                    *(float2*)(op + col) = make_float2(silu_f(C2[j][2] + s_b2[col]),
                                                       silu_f(C2[j][3] + s_b2[col + 1]));
                }
            }
        }
    }
}

extern "C" void kernel_launch(void* const* d_in, const int* in_sizes, int n_in,
                              void* d_out, int out_size) {
    const float* src   = (const float*)d_in[0];
    const float* edge  = (const float*)d_in[1];
    const float* W1    = (const float*)d_in[2];
    const float* b1    = (const float*)d_in[3];
    const float* gamma = (const float*)d_in[4];
    const float* beta  = (const float*)d_in[5];
    const float* W2    = (const float*)d_in[6];
    const float* b2    = (const float*)d_in[7];
    float* out = (float*)d_out;

    int E = in_sizes[0] / NODE_DIM;
    int num_tiles = (E + CTA_M - 1) / CTA_M;

    static int smem_set = 0;
    if (!smem_set) {
        cudaFuncSetAttribute(edge_mlp_kernel, cudaFuncAttributeMaxDynamicSharedMemorySize, SMEM_BYTES);
        smem_set = 1;
    }
    int grid = num_tiles < 152 ? num_tiles : 152;
    edge_mlp_kernel<<<grid, THREADS, SMEM_BYTES>>>(src, edge, W1, b1, gamma, beta, W2, b2,
                                                   out, E, num_tiles);
}

// round 14
// speedup vs baseline: 1.1528x; 1.1528x over previous
#include <cuda_runtime.h>
#include <cuda_fp16.h>
#include <cstdint>

#define NODE_DIM 128
#define EDGE_DIM 64
#define K1       192
#define N_OUT    128
#define WARP_M   16
#define NWARPS   16
#define THREADS  (NWARPS * 32)         // 512
#define CTA_M    (NWARPS * WARP_M)     // 256
#define W1_LD    200   // padded row stride (elems); 400B = 16 mod 128 -> LDSM conflict-free
#define W2_LD    136   // padded row stride (elems); 272B = 16 mod 128 -> LDSM conflict-free
#define LN_EPS   1e-5f

// ---- smem layout (bytes) ----
#define SM_W1H  0
#define SM_W2H  (SM_W1H + 128 * W1_LD * 2)    // 51200
#define SM_VEC  (SM_W2H + 128 * W2_LD * 2)    // 86016 : b1,b2,gamma,beta (128 f32 each)
#define SMEM_BYTES (SM_VEC + 4 * 128 * 4)     // 88064

__device__ __forceinline__ uint32_t smem_u32(const void* p) {
    uint32_t a;
    asm("{ .reg .u64 t; cvta.to.shared.u64 t, %1; cvt.u32.u64 %0, t; }" : "=r"(a) : "l"(p));
    return a;
}

// fp16 mma with fp32 accumulate (same fragment layout as bf16 variant)
__device__ __forceinline__ void mma16816(float* d, const uint32_t* a, uint32_t b0, uint32_t b1) {
    asm volatile(
        "mma.sync.aligned.m16n8k16.row.col.f32.f16.f16.f32 "
        "{%0,%1,%2,%3},{%4,%5,%6,%7},{%8,%9},{%0,%1,%2,%3};"
        : "+f"(d[0]), "+f"(d[1]), "+f"(d[2]), "+f"(d[3])
        : "r"(a[0]), "r"(a[1]), "r"(a[2]), "r"(a[3]), "r"(b0), "r"(b1));
}

// ldmatrix.x2: r0 = k-half 0 (lanes 0-7 rows), r1 = k-half 1 (lanes 8-15 rows)
__device__ __forceinline__ void ldsm_x2(uint32_t& r0, uint32_t& r1, uint32_t addr) {
    asm volatile("ldmatrix.sync.aligned.m8n8.x2.shared.b16 {%0,%1}, [%2];"
                 : "=r"(r0), "=r"(r1) : "r"(addr));
}

__device__ __forceinline__ void prefetch_l2(const void* p) {
    asm volatile("prefetch.global.L2 [%0];" :: "l"(p));
}

__device__ __forceinline__ uint32_t pack_h2(float x, float y) {
    __half2 h = __floats2half2_rn(x, y);
    return reinterpret_cast<uint32_t&>(h);
}

// exact silu: 2 MUFU
__device__ __forceinline__ float silu_f(float x) {
    return __fdividef(x, 1.0f + __expf(-x));
}

__global__ __launch_bounds__(THREADS, 1)
void edge_mlp_kernel(const float* __restrict__ src, const float* __restrict__ edge,
                     const float* __restrict__ W1, const float* __restrict__ b1v,
                     const float* __restrict__ gammav, const float* __restrict__ betav,
                     const float* __restrict__ W2, const float* __restrict__ b2v,
                     float* __restrict__ out, int E, int num_tiles)
{
    extern __shared__ char smem[];
    __half* w1h = reinterpret_cast<__half*>(smem + SM_W1H);
    __half* w2h = reinterpret_cast<__half*>(smem + SM_W2H);
    float* s_b1 = reinterpret_cast<float*>(smem + SM_VEC);
    float* s_b2 = s_b1 + 128;
    float* s_g  = s_b1 + 256;
    float* s_bt = s_b1 + 384;

    const int tid  = threadIdx.x;
    const int lane = tid & 31;
    const int wid  = tid >> 5;
    const int g    = lane >> 2;   // 0..7
    const int t    = lane & 3;    // 0..3

    // ---- one-time weight conversion into smem (fp16, transposed, padded) ----
    for (int i = tid; i < 128 * K1; i += THREADS) {
        int n = i / K1, k = i - n * K1;
        w1h[n * W1_LD + k] = __float2half_rn(W1[k * N_OUT + n]);
    }
    for (int i = tid; i < 128 * 128; i += THREADS) {
        int n = i >> 7, k = i & 127;
        w2h[n * W2_LD + k] = __float2half_rn(W2[k * N_OUT + n]);
    }
    if (tid < 128) {
        s_b1[tid] = b1v[tid];
        s_b2[tid] = b2v[tid];
        s_g[tid]  = gammav[tid];
        s_bt[tid] = betav[tid];
    }
    __syncthreads();

    // ---- per-lane ldmatrix base offsets (bytes); lanes 0-15 meaningful for x2 ----
    const int lrow  = lane & 7;
    const int lhalf = (lane >> 3) & 1;
    const uint32_t w1_base = smem_u32(smem) + SM_W1H
                           + (uint32_t)(lrow * (W1_LD * 2) + lhalf * 16);
    const uint32_t w2_base = smem_u32(smem) + SM_W2H
                           + (uint32_t)(lrow * (W2_LD * 2) + lhalf * 16);

    for (int tile = blockIdx.x; tile < num_tiles; tile += gridDim.x) {
        // ---- prefetch next tile's x rows into L2 ----
        {
            int ntile = tile + gridDim.x;
            if (ntile < num_tiles) {
                int pr = ntile * CTA_M + wid * WARP_M + (lane >> 1);
                if (pr < E) {
                    const char* ps = (const char*)(src + (size_t)pr * NODE_DIM) + (lane & 1) * 256;
                    prefetch_l2(ps);
                    prefetch_l2(ps + 128);
                    const char* pe = (const char*)(edge + (size_t)pr * EDGE_DIM) + (lane & 1) * 128;
                    prefetch_l2(pe);
                }
            }
        }

        const int rbase = tile * CTA_M + wid * WARP_M;
        int  row0 = rbase + g;
        int  row1 = rbase + 8 + g;
        bool v0 = row0 < E, v1 = row1 < E;
        const float* sp0 = src  + (size_t)(v0 ? row0 : 0) * NODE_DIM;
        const float* sp1 = src  + (size_t)(v1 ? row1 : 0) * NODE_DIM;
        const float* ep0 = edge + (size_t)(v0 ? row0 : 0) * EDGE_DIM;
        const float* ep1 = edge + (size_t)(v1 ? row1 : 0) * EDGE_DIM;

        auto loadA = [&](int s, float2* L) {
            const float2 z = make_float2(0.f, 0.f);
            const float* p0;
            const float* p1;
            int c;
            if (s < 8) { c = 16 * s + 2 * t;       p0 = sp0 + c; p1 = sp1 + c; }
            else       { c = 16 * s - 128 + 2 * t; p0 = ep0 + c; p1 = ep1 + c; }
            L[0] = v0 ? *(const float2*)(p0)     : z;
            L[1] = v1 ? *(const float2*)(p1)     : z;
            L[2] = v0 ? *(const float2*)(p0 + 8) : z;
            L[3] = v1 ? *(const float2*)(p1 + 8) : z;
        };

        // ================= GEMM1: C1 = x(192) @ W1, single-pass fp16 =================
        float C1[16][4];
        #pragma unroll
        for (int j = 0; j < 16; ++j)
            #pragma unroll
            for (int q = 0; q < 4; ++q) C1[j][q] = 0.f;

        float2 cur[4], nxt[4];
        loadA(0, cur);
        #pragma unroll 1
        for (int s = 0; s < 12; ++s) {
            if (s < 11) loadA(s + 1, nxt);
            uint32_t a[4];
            #pragma unroll
            for (int q = 0; q < 4; ++q) a[q] = pack_h2(cur[q].x, cur[q].y);
            const uint32_t base_s = w1_base + (uint32_t)(s * 32);
            #pragma unroll
            for (int j = 0; j < 16; ++j) {
                uint32_t b0, b1;
                ldsm_x2(b0, b1, base_s + (uint32_t)(j * (8 * W1_LD * 2)));
                mma16816(C1[j], a, b0, b1);
            }
            #pragma unroll
            for (int q = 0; q < 4; ++q) cur[q] = nxt[q];
        }

        // ============ Epilogue 1: +b1, LayerNorm (2x shfl over t), SiLU, pack fp16 ============
        uint32_t A2h[2][16];
        #pragma unroll
        for (int i = 0; i < 2; ++i) {
            float sum = 0.f, ssq = 0.f;
            #pragma unroll
            for (int j = 0; j < 16; ++j) {
                const int col = 8 * j + 2 * t;
                float x0 = C1[j][2 * i + 0] + s_b1[col];
                float x1 = C1[j][2 * i + 1] + s_b1[col + 1];
                C1[j][2 * i + 0] = x0;
                C1[j][2 * i + 1] = x1;
                sum += x0 + x1;
                ssq = fmaf(x0, x0, ssq);
                ssq = fmaf(x1, x1, ssq);
            }
            sum += __shfl_xor_sync(0xffffffffu, sum, 1);
            sum += __shfl_xor_sync(0xffffffffu, sum, 2);
            ssq += __shfl_xor_sync(0xffffffffu, ssq, 1);
            ssq += __shfl_xor_sync(0xffffffffu, ssq, 2);
            float mu  = sum * (1.f / 128.f);
            float var = ssq * (1.f / 128.f) - mu * mu;
            float rs  = rsqrtf(fmaxf(var, 0.f) + LN_EPS);
            #pragma unroll
            for (int j = 0; j < 16; ++j) {
                const int col = 8 * j + 2 * t;
                float y0 = (C1[j][2 * i + 0] - mu) * rs * s_g[col]     + s_bt[col];
                float y1 = (C1[j][2 * i + 1] - mu) * rs * s_g[col + 1] + s_bt[col + 1];
                y0 = silu_f(y0);
                y1 = silu_f(y1);
                A2h[i][j] = pack_h2(y0, y1);
            }
        }

        // ================= GEMM2 (n-split halves): out = silu(h @ W2 + b2) =================
        #pragma unroll 1
        for (int hf = 0; hf < 2; ++hf) {
            float C2[8][4];
            #pragma unroll
            for (int j = 0; j < 8; ++j)
                #pragma unroll
                for (int q = 0; q < 4; ++q) C2[j][q] = 0.f;

            const uint32_t base_hf = w2_base + (uint32_t)(hf * (64 * W2_LD * 2));
            #pragma unroll
            for (int s = 0; s < 8; ++s) {
                uint32_t a[4];
                a[0] = A2h[0][2 * s];     a[1] = A2h[1][2 * s];
                a[2] = A2h[0][2 * s + 1]; a[3] = A2h[1][2 * s + 1];
                const uint32_t base_s = base_hf + (uint32_t)(s * 32);
                #pragma unroll
                for (int j = 0; j < 8; ++j) {
                    uint32_t b0, b1;
                    ldsm_x2(b0, b1, base_s + (uint32_t)(j * (8 * W2_LD * 2)));
                    mma16816(C2[j], a, b0, b1);
                }
            }

            if (v0) {
                float* op = out + (size_t)row0 * N_OUT;
                #pragma unroll
                for (int j = 0; j < 8; ++j) {
                    const int col = hf * 64 + 8 * j + 2 * t;
                    *(float2*)(op + col) = make_float2(silu_f(C2[j][0] + s_b2[col]),
                                                       silu_f(C2[j][1] + s_b2[col + 1]));
                }
            }
            if (v1) {
                float* op = out + (size_t)row1 * N_OUT;
                #pragma unroll
                for (int j = 0; j < 8; ++j) {
                    const int col = hf * 64 + 8 * j + 2 * t;
                    *(float2*)(op + col) = make_float2(silu_f(C2[j][2] + s_b2[col]),
                                                       silu_f(C2[j][3] + s_b2[col + 1]));
                }
            }
        }
    }
}

extern "C" void kernel_launch(void* const* d_in, const int* in_sizes, int n_in,
                              void* d_out, int out_size) {
    const float* src   = (const float*)d_in[0];
    const float* edge  = (const float*)d_in[1];
    const float* W1    = (const float*)d_in[2];
    const float* b1    = (const float*)d_in[3];
    const float* gamma = (const float*)d_in[4];
    const float* beta  = (const float*)d_in[5];
    const float* W2    = (const float*)d_in[6];
    const float* b2    = (const float*)d_in[7];
    float* out = (float*)d_out;

    int E = in_sizes[0] / NODE_DIM;
    int num_tiles = (E + CTA_M - 1) / CTA_M;

    static int smem_set = 0;
    if (!smem_set) {
        cudaFuncSetAttribute(edge_mlp_kernel, cudaFuncAttributeMaxDynamicSharedMemorySize, SMEM_BYTES);
        smem_set = 1;
    }
    int grid = num_tiles < 152 ? num_tiles : 152;
    edge_mlp_kernel<<<grid, THREADS, SMEM_BYTES>>>(src, edge, W1, b1, gamma, beta, W2, b2,
                                                   out, E, num_tiles);
}